// round 1
// baseline (speedup 1.0000x reference)
#include <cuda_runtime.h>
#include <math.h>

#define NB 2
#define NT 32
#define NI 2048
#define NF 64
#define TWOF 128
#define NL 5
#define NSPLIT 16
#define CHUNK 128
#define TM1 31

#define RT_SIZE (NB*NI*TWOF)          // 524288
#define MT_OFF  RT_SIZE
#define LOSS_OFF (RT_SIZE + NB*TWOF)  // 524544

// ---------------- scratch (device globals: allocation-free) ----------------
__device__ float g_rh[NB*NT*NI*NF];           // r_hist, 33.5 MB
__device__ float g_eta[NB*NT*NI];
__device__ float g_c[NI];                     // Wiota[i] . w_eta
__device__ unsigned char g_member[NT*NI];     // 0 = S1 (first half of perm), 1 = S2
__device__ int   g_cnt_pos[NB*TM1];
__device__ int   g_cnt_neg[NB*TM1];
__device__ float g_mpart[NB*NT*NSPLIT*2*TWOF];
__device__ float g_a1[NB*NT];
__device__ float g_a2[NB*NT];
__device__ float g_mall[NB*NT*TWOF];
__device__ float g_sync[NB*TM1];

__device__ __forceinline__ float warp_sum(float v){
  #pragma unroll
  for (int o = 16; o > 0; o >>= 1) v += __shfl_xor_sync(0xffffffffu, v, o);
  return v;
}

__device__ __forceinline__ float block_reduce(float v, float* red){
  int tid = threadIdx.x;
  red[tid] = v; __syncthreads();
  for (int off = blockDim.x >> 1; off > 0; off >>= 1){
    if (tid < off) red[tid] += red[tid + off];
    __syncthreads();
  }
  float r = red[0];
  __syncthreads();
  return r;
}

// ---------------- K0: c_i = Wiota[i,:] . w_eta ----------------
__global__ void k_iota(const float* __restrict__ Wiota, const float* __restrict__ w_eta){
  int i = blockIdx.x * blockDim.x + threadIdx.x;
  if (i < NI){
    float s = 0.f;
    #pragma unroll 8
    for (int f = 0; f < TWOF; f++) s += Wiota[i*TWOF + f] * w_eta[f];
    g_c[i] = s;
  }
}

// ---------------- K0b: membership bit from perms ----------------
__global__ void k_mask(const int* __restrict__ perms){
  int t = blockIdx.x;
  for (int j = threadIdx.x; j < NI; j += blockDim.x){
    int p = perms[t*NI + j];
    g_member[t*NI + p] = (unsigned char)(j >= NI/2);
  }
}

// ---------------- K0c: zero count accumulators ----------------
__global__ void k_zero(){
  int tid = threadIdx.x;
  if (tid < NB*TM1){ g_cnt_pos[tid] = 0; g_cnt_neg[tid] = 0; }
}

// ---------------- K2: fused per-(b,i): k-gemm, window attention, r_hist, eta, r_t, counts ----
__global__ __launch_bounds__(256) void k_main(
    const float* __restrict__ e_seq, const float* __restrict__ Ws_w,
    const float* __restrict__ Ws_b, const float* __restrict__ w_eta,
    const int* __restrict__ close_idx_p, float* __restrict__ d_out)
{
  __shared__ float Ws[64*65];   // padded stride 65
  __shared__ float Es[32*66];   // padded stride 66
  __shared__ float Ks[32*65];   // padded stride 65
  __shared__ float We[TWOF];
  __shared__ float Bs[NF];

  int i = blockIdx.x, b = blockIdx.y;
  int tid = threadIdx.x;

  for (int x = tid; x < 4096; x += 256) Ws[(x >> 6)*65 + (x & 63)] = Ws_w[x];
  if (tid < TWOF) We[tid] = w_eta[tid];
  if (tid < NF)   Bs[tid] = Ws_b[tid];

  const float* ebase = e_seq + ((size_t)b*NT*NI + i)*NF;
  for (int x = tid; x < NT*NF; x += 256){
    int t = x >> 6, f = x & 63;
    Es[t*66 + f] = ebase[(size_t)t*NI*NF + f];
  }
  __syncthreads();

  int warp = tid >> 5, lane = tid & 31;

  // return-sign counts (warp 0): sign of c[t+1]/(c[t]+1e-8) vs 1.0
  if (warp == 0 && lane < TM1){
    int cidx = *close_idx_p;
    float c0 = Es[lane*66 + cidx];
    float c1 = Es[(lane+1)*66 + cidx];
    float r = c1 / (c0 + 1e-8f);
    if (r > 1.0f)      atomicAdd(&g_cnt_pos[b*TM1 + lane], 1);
    else if (r < 1.0f) atomicAdd(&g_cnt_neg[b*TM1 + lane], 1);
  }

  // k = e @ Ws^T + b, register-tiled: thread -> t in {trow,trow+16}, fo in {fog+16j}
  {
    int fog  = tid & 15;
    int trow = tid >> 4;
    float acc0[4], acc1[4];
    #pragma unroll
    for (int j = 0; j < 4; j++){ acc0[j] = Bs[fog + 16*j]; acc1[j] = acc0[j]; }
    #pragma unroll 4
    for (int f = 0; f < 64; f++){
      float ea = Es[trow*66 + f];
      float eb = Es[(trow+16)*66 + f];
      #pragma unroll
      for (int j = 0; j < 4; j++){
        float w = Ws[(fog + 16*j)*65 + f];
        acc0[j] += ea * w;
        acc1[j] += eb * w;
      }
    }
    #pragma unroll
    for (int j = 0; j < 4; j++){
      Ks[trow*65 + fog + 16*j]      = acc0[j];
      Ks[(trow+16)*65 + fog + 16*j] = acc1[j];
    }
  }
  __syncthreads();

  float ci = g_c[i];

  // attention window + r_hist + eta; warp handles t = warp, warp+8, ...
  for (int tt = warp; tt < NT; tt += 8){
    float kq0 = Ks[tt*65 + lane];
    float kq1 = Ks[tt*65 + 32 + lane];
    float s[NL];
    #pragma unroll
    for (int l = 0; l < NL; l++){
      int tl = tt - 4 + l;
      float p = -1e30f;
      if (tl >= 0){
        float v = kq0*Ks[tl*65 + lane] + kq1*Ks[tl*65 + 32 + lane];
        v = warp_sum(v);
        p = v * 0.125f;          // / sqrt(64)
      }
      s[l] = p;
    }
    float mx = s[0];
    #pragma unroll
    for (int l = 1; l < NL; l++) mx = fmaxf(mx, s[l]);
    float pe[NL], psum = 0.f;
    #pragma unroll
    for (int l = 0; l < NL; l++){ pe[l] = expf(s[l] - mx); psum += pe[l]; }
    float inv = 1.0f / psum;
    float rh0 = 0.f, rh1 = 0.f;
    #pragma unroll
    for (int l = 0; l < NL; l++){
      int tl = tt - 4 + l; if (tl < 0) tl = 0;
      float a = pe[l] * inv;
      rh0 += a * Es[tl*66 + lane];
      rh1 += a * Es[tl*66 + 32 + lane];
    }
    size_t rbase = (((size_t)b*NT + tt)*NI + i)*NF;
    g_rh[rbase + lane]      = rh0;
    g_rh[rbase + 32 + lane] = rh1;

    float e0 = Es[tt*66 + lane], e1 = Es[tt*66 + 32 + lane];
    float d = e0*We[lane] + e1*We[32+lane] + rh0*We[64+lane] + rh1*We[96+lane];
    d = warp_sum(d);
    float eta = fmaxf(d + ci, 0.f);
    if (lane == 0) g_eta[((size_t)b*NT + tt)*NI + i] = eta;

    if (tt == NT-1){
      float* ro = d_out + ((size_t)b*NI + i)*TWOF;
      ro[lane] = e0; ro[32+lane] = e1; ro[64+lane] = rh0; ro[96+lane] = rh1;
    }
  }
}

// ---------------- K3: partial masked sums of eta * r_all over i chunks ----------------
__global__ __launch_bounds__(128) void k_msum(const float* __restrict__ e_seq){
  int bt = blockIdx.x;
  int t  = bt % NT;
  int s  = blockIdx.y;
  int tid = threadIdx.x;
  __shared__ float eta_s[CHUNK];
  __shared__ unsigned char mem_s[CHUNK];
  int i0 = s * CHUNK;
  if (tid < CHUNK){
    eta_s[tid] = g_eta[(size_t)bt*NI + i0 + tid];
    mem_s[tid] = g_member[t*NI + i0 + tid];
  }
  __syncthreads();
  float a1 = 0.f, a2 = 0.f;
  const float* erow = e_seq + ((size_t)bt*NI + i0)*NF;
  const float* rrow = g_rh  + ((size_t)bt*NI + i0)*NF;
  bool hi = tid >= NF;
  int f = tid & (NF-1);
  #pragma unroll 4
  for (int j = 0; j < CHUNK; j++){
    float r = hi ? rrow[(size_t)j*NF + f] : erow[(size_t)j*NF + f];
    float ev = eta_s[j];
    float w2 = mem_s[j] ? ev : 0.f;
    a2 += w2 * r;
    a1 += (ev - w2) * r;
  }
  float* op = g_mpart + ((size_t)bt*NSPLIT + s)*2*TWOF;
  op[tid]        = a1;
  op[TWOF + tid] = a2;
}

// ---------------- K4: combine partials -> m1, m2, m_all, l2n, a1, a2, m_t ----------------
__global__ __launch_bounds__(256) void k_mfinal(const float* __restrict__ w_M,
                                                float* __restrict__ d_out){
  int bt = blockIdx.x;
  int b = bt / NT, t = bt % NT;
  int tid = threadIdx.x;
  __shared__ float red[256];
  __shared__ float m1s[TWOF], m2s[TWOF];
  __shared__ float dens[2];

  float d1 = 0.f, d2 = 0.f;
  for (int ii = tid; ii < NI; ii += 256){
    float ev = g_eta[(size_t)bt*NI + ii];
    if (g_member[t*NI + ii]) d2 += ev; else d1 += ev;
  }
  float D1 = block_reduce(d1, red);
  float D2 = block_reduce(d2, red);
  if (tid == 0){ dens[0] = D1; dens[1] = D2; }
  __syncthreads();

  if (tid < TWOF){
    float n1 = 0.f, n2 = 0.f;
    #pragma unroll
    for (int s = 0; s < NSPLIT; s++){
      const float* p = g_mpart + ((size_t)bt*NSPLIT + s)*2*TWOF;
      n1 += p[tid];
      n2 += p[TWOF + tid];
    }
    float m1 = n1 / (dens[0] + 1e-6f);
    float m2 = n2 / (dens[1] + 1e-6f);
    m1s[tid] = m1; m2s[tid] = m2;
    float ma = (n1 + n2) / (dens[0] + dens[1] + 1e-6f);
    g_mall[(size_t)bt*TWOF + tid] = ma;
    if (t == NT-1) d_out[MT_OFF + b*TWOF + tid] = ma;
  }
  __syncthreads();

  float v1 = (tid < TWOF) ? m1s[tid] : 0.f;
  float v2 = (tid < TWOF) ? m2s[tid] : 0.f;
  float wm1 = (tid < TWOF) ? w_M[tid] : 0.f;
  float wm2 = (tid < TWOF) ? w_M[TWOF + tid] : 0.f;
  float sq1 = block_reduce(v1*v1, red);
  float dt1 = block_reduce(v1*wm1, red);
  float sq2 = block_reduce(v2*v2, red);
  float dt2 = block_reduce(v2*wm2, red);
  if (tid == 0){
    g_a1[bt] = dt1 / fmaxf(sqrtf(sq1), 1e-12f);
    g_a2[bt] = dt2 / fmaxf(sqrtf(sq2), 1e-12f);
  }
}

// ---------------- K5: per-(b,t) sync-loss rows ----------------
__global__ __launch_bounds__(128) void k_sync(
    const float* __restrict__ sc_W1, const float* __restrict__ sc_b1,
    const float* __restrict__ sc_W2, const float* __restrict__ sc_b2)
{
  int x = blockIdx.x;
  int b = x / TM1, t = x % TM1;
  int tid = threadIdx.x;
  __shared__ float ms[TWOF];
  __shared__ float hs[TWOF];
  __shared__ float lg[3];

  ms[tid] = g_mall[(size_t)(b*NT + t)*TWOF + tid];
  __syncthreads();

  float acc = sc_b1[tid];
  #pragma unroll 8
  for (int k = 0; k < TWOF; k++) acc += __ldg(&sc_W1[tid*TWOF + k]) * ms[k];
  hs[tid] = fmaxf(acc, 0.f);
  __syncthreads();

  int warp = tid >> 5, lane = tid & 31;
  if (warp < 3){
    float p = 0.f;
    #pragma unroll
    for (int j = lane; j < TWOF; j += 32) p += hs[j] * __ldg(&sc_W2[warp*TWOF + j]);
    p = warp_sum(p);
    if (lane == 0) lg[warp] = p + sc_b2[warp];
  }
  __syncthreads();

  if (tid == 0){
    int cp = g_cnt_pos[b*TM1 + t], cn = g_cnt_neg[b*TM1 + t];
    float pr = (float)cp * (1.0f/NI);
    float nr = (float)cn * (1.0f/NI);
    int lbl = (pr >= 0.6f) ? 0 : ((nr >= 0.6f) ? 1 : 2);
    float mx = fmaxf(lg[0], fmaxf(lg[1], lg[2]));
    float lse = logf(expf(lg[0]-mx) + expf(lg[1]-mx) + expf(lg[2]-mx)) + mx;
    g_sync[x] = lse - lg[lbl];
  }
}

// ---------------- K6: contrast loss + combine ----------------
__global__ __launch_bounds__(256) void k_final(const float* __restrict__ b_M,
                                               float* __restrict__ d_out){
  int tid = threadIdx.x;
  __shared__ float red[256];
  float bm = *b_M;
  float acc = 0.f;
  if (tid < NT*NB){
    int t1 = tid & (NT-1), b = tid >> 5;
    float a1v = g_a1[b*NT + t1];
    float sum = 0.f, pos = 0.f;
    #pragma unroll 4
    for (int t2 = 0; t2 < NT; t2++){
      float sc = a1v + g_a2[b*NT + t2] + bm;
      sc = fminf(fmaxf(sc, -10.f), 10.f);
      float tw = 1.0f / (fabsf((float)(t1 - t2)) + 1.0f);
      float w = expf(sc * tw);
      sum += w;
      if (t2 == t1) pos = w;
    }
    acc = logf(sum + 1e-8f) - logf(pos);
  }
  float lc = block_reduce(acc, red) * (1.0f/(NT*NB));
  float sv = (tid < NB*TM1) ? g_sync[tid] : 0.f;
  float ls = block_reduce(sv, red) * (1.0f/(NB*TM1));
  if (tid == 0) d_out[LOSS_OFF] = lc + ls;
}

// ---------------- launch ----------------
extern "C" void kernel_launch(void* const* d_in, const int* in_sizes, int n_in,
                              void* d_out, int out_size){
  const float* e_seq = (const float*)d_in[0];
  // d_in[1] = stockID (identity; folded into k_iota using Wiota directly)
  const float* Ws_w  = (const float*)d_in[2];
  const float* Ws_b  = (const float*)d_in[3];
  const float* Wiota = (const float*)d_in[4];
  const float* w_eta = (const float*)d_in[5];
  const float* w_M   = (const float*)d_in[6];
  const float* b_M   = (const float*)d_in[7];
  const float* sc_W1 = (const float*)d_in[8];
  const float* sc_b1 = (const float*)d_in[9];
  const float* sc_W2 = (const float*)d_in[10];
  const float* sc_b2 = (const float*)d_in[11];
  const int*  perms  = (const int*)d_in[12];
  const int*  cidx   = (const int*)d_in[13];
  float* out = (float*)d_out;

  k_iota<<<(NI+255)/256, 256>>>(Wiota, w_eta);
  k_mask<<<NT, 256>>>(perms);
  k_zero<<<1, 64>>>();
  k_main<<<dim3(NI, NB), 256>>>(e_seq, Ws_w, Ws_b, w_eta, cidx, out);
  k_msum<<<dim3(NB*NT, NSPLIT), 128>>>(e_seq);
  k_mfinal<<<NB*NT, 256>>>(w_M, out);
  k_sync<<<NB*TM1, 128>>>(sc_W1, sc_b1, sc_W2, sc_b2);
  k_final<<<1, 256>>>(b_M, out);
}

// round 2
// speedup vs baseline: 1.4020x; 1.4020x over previous
#include <cuda_runtime.h>
#include <math.h>

#define NB 2
#define NT 32
#define NI 2048
#define NF 64
#define TWOF 128
#define NL 5
#define NSPLIT 16
#define CHUNK 128
#define TM1 31
#define MP_STRIDE 264   // 2*TWOF + 2 dens, padded to mult of 4

#define RT_SIZE (NB*NI*TWOF)          // 524288
#define MT_OFF  RT_SIZE
#define LOSS_OFF (RT_SIZE + NB*TWOF)  // 524544

// ---------------- scratch (device globals: allocation-free) ----------------
__device__ float g_rh[NB*NT*NI*NF];           // r_hist
__device__ float g_eta[NB*NT*NI];
__device__ float g_c[NI];                     // Wiota[i] . w_eta
__device__ unsigned char g_member[NT*NI];     // 0 = S1, 1 = S2
__device__ int   g_cnt_pos[NB*TM1];
__device__ int   g_cnt_neg[NB*TM1];
__device__ float g_mpart[NB*NT*NSPLIT*MP_STRIDE];
__device__ float g_a1[NB*NT];
__device__ float g_a2[NB*NT];
__device__ float g_sync[NB*TM1];

__device__ __forceinline__ float warp_sum(float v){
  #pragma unroll
  for (int o = 16; o > 0; o >>= 1) v += __shfl_xor_sync(0xffffffffu, v, o);
  return v;
}

__device__ __forceinline__ float block_reduce(float v, float* red){
  int tid = threadIdx.x;
  red[tid] = v; __syncthreads();
  for (int off = blockDim.x >> 1; off > 0; off >>= 1){
    if (tid < off) red[tid] += red[tid + off];
    __syncthreads();
  }
  float r = red[0];
  __syncthreads();
  return r;
}

// ---------------- K_pre: iota dot + membership + counter zero, one launch ----
__global__ void k_pre(const float* __restrict__ Wiota, const float* __restrict__ w_eta,
                      const int* __restrict__ perms){
  int bx = blockIdx.x;
  int tid = threadIdx.x;
  if (bx < 8){
    int i = bx*256 + tid;
    float s = 0.f;
    const float4* wi = (const float4*)(Wiota + (size_t)i*TWOF);
    const float4* we = (const float4*)w_eta;
    #pragma unroll 8
    for (int q = 0; q < 32; q++){
      float4 a = wi[q], b = we[q];
      s += a.x*b.x + a.y*b.y + a.z*b.z + a.w*b.w;
    }
    g_c[i] = s;
  } else if (bx < 40){
    int t = bx - 8;
    for (int j = tid; j < NI; j += 256){
      int p = perms[t*NI + j];
      g_member[t*NI + p] = (unsigned char)(j >= NI/2);
    }
  } else {
    if (tid < NB*TM1){ g_cnt_pos[tid] = 0; g_cnt_neg[tid] = 0; }
  }
}

// ---------------- K_main: fused per-(b,i): k-gemm(float4), window attn, r_hist, eta, r_t ----
__global__ __launch_bounds__(256) void k_main(
    const float* __restrict__ e_seq, const float* __restrict__ Ws_w,
    const float* __restrict__ Ws_b, const float* __restrict__ w_eta,
    const int* __restrict__ close_idx_p, float* __restrict__ d_out)
{
  __shared__ float4 Ws4[64*17];   // [fo][c], row stride 17 float4 = 68 floats
  __shared__ float4 Es4[32*17];   // [t][c],  row stride 17 float4 = 68 floats
  __shared__ float  Ks[32*66];
  __shared__ float  We[TWOF];
  __shared__ float  Bs[NF];

  int i = blockIdx.x, b = blockIdx.y;
  int tid = threadIdx.x;
  int warp = tid >> 5, lane = tid & 31;

  // stage Ws (64x64) as float4, swizzled to stride-17
  {
    const float4* wg = (const float4*)Ws_w;
    #pragma unroll
    for (int x = tid; x < 1024; x += 256)
      Ws4[(x >> 4)*17 + (x & 15)] = wg[x];
  }
  if (tid < TWOF) We[tid] = w_eta[tid];
  if (tid < NF)   Bs[tid] = Ws_b[tid];

  // stage e (32x64) as float4
  {
    const float4* eg = (const float4*)(e_seq + ((size_t)b*NT*NI + i)*NF);
    #pragma unroll
    for (int x = tid; x < 512; x += 256){
      int t = x >> 4, c = x & 15;
      Es4[t*17 + c] = eg[(size_t)t*(NI*16) + c];
    }
  }
  __syncthreads();

  const float* Esf = (const float*)Es4;   // stride 68 floats

  // return-sign counts (warp 0)
  if (warp == 0 && lane < TM1){
    int cidx = *close_idx_p;
    float c0 = Esf[lane*68 + cidx];
    float c1 = Esf[(lane+1)*68 + cidx];
    float r = c1 / (c0 + 1e-8f);
    if (r > 1.0f)      atomicAdd(&g_cnt_pos[b*TM1 + lane], 1);
    else if (r < 1.0f) atomicAdd(&g_cnt_neg[b*TM1 + lane], 1);
  }

  // k = e @ Ws^T + b. Warp w: t in [4w,4w+4), lane computes fo=lane and fo=lane+32.
  {
    int t0 = warp * 4;
    float b0 = Bs[lane], b1 = Bs[lane + 32];
    float acc[4][2];
    #pragma unroll
    for (int r = 0; r < 4; r++){ acc[r][0] = b0; acc[r][1] = b1; }
    #pragma unroll
    for (int c = 0; c < 16; c++){
      float4 w0 = Ws4[lane*17 + c];
      float4 w1 = Ws4[(lane+32)*17 + c];
      #pragma unroll
      for (int r = 0; r < 4; r++){
        float4 ev = Es4[(t0+r)*17 + c];
        acc[r][0] += ev.x*w0.x + ev.y*w0.y + ev.z*w0.z + ev.w*w0.w;
        acc[r][1] += ev.x*w1.x + ev.y*w1.y + ev.z*w1.z + ev.w*w1.w;
      }
    }
    #pragma unroll
    for (int r = 0; r < 4; r++){
      Ks[(t0+r)*66 + lane]      = acc[r][0];
      Ks[(t0+r)*66 + 32 + lane] = acc[r][1];
    }
  }
  __syncthreads();

  float ci = g_c[i];
  float we0 = We[lane], we1 = We[32+lane], we2 = We[64+lane], we3 = We[96+lane];

  // attention window + r_hist + eta; warp handles t = warp, warp+8, ...
  for (int tt = warp; tt < NT; tt += 8){
    float kq0 = Ks[tt*66 + lane];
    float kq1 = Ks[tt*66 + 32 + lane];
    float s[NL];
    #pragma unroll
    for (int l = 0; l < NL; l++){
      int tl = tt - 4 + l;
      float p = -1e30f;
      if (tl >= 0){
        float v = kq0*Ks[tl*66 + lane] + kq1*Ks[tl*66 + 32 + lane];
        v = warp_sum(v);
        p = v * 0.125f;          // / sqrt(64)
      }
      s[l] = p;
    }
    float mx = s[0];
    #pragma unroll
    for (int l = 1; l < NL; l++) mx = fmaxf(mx, s[l]);
    float pe[NL], psum = 0.f;
    #pragma unroll
    for (int l = 0; l < NL; l++){ pe[l] = expf(s[l] - mx); psum += pe[l]; }
    float inv = 1.0f / psum;
    float rh0 = 0.f, rh1 = 0.f;
    #pragma unroll
    for (int l = 0; l < NL; l++){
      int tl = tt - 4 + l; if (tl < 0) tl = 0;
      float a = pe[l] * inv;
      rh0 += a * Esf[tl*68 + lane];
      rh1 += a * Esf[tl*68 + 32 + lane];
    }
    size_t rbase = (((size_t)b*NT + tt)*NI + i)*NF;
    g_rh[rbase + lane]      = rh0;
    g_rh[rbase + 32 + lane] = rh1;

    float e0 = Esf[tt*68 + lane], e1 = Esf[tt*68 + 32 + lane];
    float d = e0*we0 + e1*we1 + rh0*we2 + rh1*we3;
    d = warp_sum(d);
    float eta = fmaxf(d + ci, 0.f);
    if (lane == 0) g_eta[((size_t)b*NT + tt)*NI + i] = eta;

    if (tt == NT-1){
      float* ro = d_out + ((size_t)b*NI + i)*TWOF;
      ro[lane] = e0; ro[32+lane] = e1; ro[64+lane] = rh0; ro[96+lane] = rh1;
    }
  }
}

// ---------------- K_msum: masked partial sums of eta * r_all (float4) + dens ----
__global__ __launch_bounds__(128) void k_msum(const float* __restrict__ e_seq){
  int bt = blockIdx.x;
  int t  = bt % NT;
  int s  = blockIdx.y;
  int tid = threadIdx.x;
  __shared__ float eta_s[CHUNK];
  __shared__ float w2_s[CHUNK];
  __shared__ float4 red[256];
  int i0 = s * CHUNK;
  if (tid < CHUNK){
    float e = g_eta[(size_t)bt*NI + i0 + tid];
    eta_s[tid] = e;
    w2_s[tid]  = g_member[t*NI + i0 + tid] ? e : 0.f;
  }
  __syncthreads();

  int fq = tid & 31;     // float4 index over 128-f r_all: fq<16 -> e half, else rh half
  int jb = tid >> 5;     // 0..3
  bool hi = fq >= 16;
  int c = hi ? fq - 16 : fq;
  const float* src = hi ? (g_rh + ((size_t)bt*NI + i0)*NF)
                        : (e_seq + ((size_t)bt*NI + i0)*NF);
  const float4* base = (const float4*)src;
  float4 a1 = make_float4(0.f,0.f,0.f,0.f);
  float4 a2 = make_float4(0.f,0.f,0.f,0.f);
  #pragma unroll 8
  for (int j = jb; j < CHUNK; j += 4){
    float4 r = base[(size_t)j*16 + c];
    float w2 = w2_s[j], w1 = eta_s[j] - w2;
    a1.x += w1*r.x; a1.y += w1*r.y; a1.z += w1*r.z; a1.w += w1*r.w;
    a2.x += w2*r.x; a2.y += w2*r.y; a2.z += w2*r.z; a2.w += w2*r.w;
  }
  red[tid] = a1; red[128 + tid] = a2;
  __syncthreads();

  float* op = g_mpart + ((size_t)bt*NSPLIT + s)*MP_STRIDE;
  if (tid < 64){
    int which = tid >> 5;           // 0 -> a1, 1 -> a2
    int q = tid & 31;
    float4 sum = red[which*128 + q];
    #pragma unroll
    for (int g = 1; g < 4; g++){
      float4 v = red[which*128 + 32*g + q];
      sum.x += v.x; sum.y += v.y; sum.z += v.z; sum.w += v.w;
    }
    ((float4*)(op + which*TWOF))[q] = sum;
  } else if (tid < 96){
    int l = tid - 64;
    float d1 = 0.f, d2 = 0.f;
    #pragma unroll
    for (int j = l; j < CHUNK; j += 32){ float w2 = w2_s[j]; d2 += w2; d1 += eta_s[j] - w2; }
    d1 = warp_sum(d1);
    d2 = warp_sum(d2);
    if (l == 0){ op[2*TWOF] = d1; op[2*TWOF+1] = d2; }
  }
}

// ---------------- K_mfinal: combine partials -> m1,m2,m_all, l2n dots, m_t, sync loss ----
__global__ __launch_bounds__(256) void k_mfinal(
    const float* __restrict__ w_M,
    const float* __restrict__ sc_W1, const float* __restrict__ sc_b1,
    const float* __restrict__ sc_W2, const float* __restrict__ sc_b2,
    float* __restrict__ d_out)
{
  int bt = blockIdx.x;
  int b = bt / NT, t = bt % NT;
  int tid = threadIdx.x;
  __shared__ float red[256];
  __shared__ float m1s[TWOF], m2s[TWOF], ms[TWOF], hs[TWOF];
  __shared__ float dens[2];
  __shared__ float lg[3];

  // combine partials: tid covers n1 (0..127) and n2 (128..255)
  {
    float n = 0.f;
    #pragma unroll
    for (int s = 0; s < NSPLIT; s++)
      n += g_mpart[((size_t)bt*NSPLIT + s)*MP_STRIDE + tid];
    red[tid] = n;
  }
  if (tid == 0){
    float D1 = 0.f, D2 = 0.f;
    #pragma unroll
    for (int s = 0; s < NSPLIT; s++){
      const float* p = g_mpart + ((size_t)bt*NSPLIT + s)*MP_STRIDE;
      D1 += p[2*TWOF]; D2 += p[2*TWOF+1];
    }
    dens[0] = D1; dens[1] = D2;
  }
  __syncthreads();

  if (tid < TWOF){
    float n1 = red[tid], n2 = red[TWOF + tid];
    float m1 = n1 / (dens[0] + 1e-6f);
    float m2 = n2 / (dens[1] + 1e-6f);
    m1s[tid] = m1; m2s[tid] = m2;
    float ma = (n1 + n2) / (dens[0] + dens[1] + 1e-6f);
    ms[tid] = ma;
    if (t == NT-1) d_out[MT_OFF + b*TWOF + tid] = ma;
  }
  __syncthreads();

  float v1 = (tid < TWOF) ? m1s[tid] : 0.f;
  float v2 = (tid < TWOF) ? m2s[tid] : 0.f;
  float wm1 = (tid < TWOF) ? w_M[tid] : 0.f;
  float wm2 = (tid < TWOF) ? w_M[TWOF + tid] : 0.f;
  float sq1 = block_reduce(v1*v1, red);
  float dt1 = block_reduce(v1*wm1, red);
  float sq2 = block_reduce(v2*v2, red);
  float dt2 = block_reduce(v2*wm2, red);
  if (tid == 0){
    g_a1[bt] = dt1 / fmaxf(sqrtf(sq1), 1e-12f);
    g_a2[bt] = dt2 / fmaxf(sqrtf(sq2), 1e-12f);
  }

  // sync-loss row for this (b,t) if t < T-1 (uniform branch per block)
  if (t < TM1){
    __syncthreads();
    if (tid < TWOF){
      float acc = sc_b1[tid];
      const float4* w1r = (const float4*)(sc_W1 + (size_t)tid*TWOF);
      const float4* msr = (const float4*)ms;
      #pragma unroll 8
      for (int q = 0; q < 32; q++){
        float4 a = w1r[q], m = msr[q];
        acc += a.x*m.x + a.y*m.y + a.z*m.z + a.w*m.w;
      }
      hs[tid] = fmaxf(acc, 0.f);
    }
    __syncthreads();
    int warp = tid >> 5, lane = tid & 31;
    if (warp < 3){
      float p = 0.f;
      #pragma unroll
      for (int j = lane; j < TWOF; j += 32) p += hs[j] * __ldg(&sc_W2[warp*TWOF + j]);
      p = warp_sum(p);
      if (lane == 0) lg[warp] = p + sc_b2[warp];
    }
    __syncthreads();
    if (tid == 0){
      int cp = g_cnt_pos[b*TM1 + t], cn = g_cnt_neg[b*TM1 + t];
      float pr = (float)cp * (1.0f/NI);
      float nr = (float)cn * (1.0f/NI);
      int lbl = (pr >= 0.6f) ? 0 : ((nr >= 0.6f) ? 1 : 2);
      float mx = fmaxf(lg[0], fmaxf(lg[1], lg[2]));
      float lse = logf(expf(lg[0]-mx) + expf(lg[1]-mx) + expf(lg[2]-mx)) + mx;
      g_sync[b*TM1 + t] = lse - lg[lbl];
    }
  }
}

// ---------------- K_final: contrast loss + combine ----------------
__global__ __launch_bounds__(256) void k_final(const float* __restrict__ b_M,
                                               float* __restrict__ d_out){
  int tid = threadIdx.x;
  __shared__ float red[256];
  float bm = *b_M;
  float acc = 0.f;
  if (tid < NT*NB){
    int t1 = tid & (NT-1), b = tid >> 5;
    float a1v = g_a1[b*NT + t1];
    float sum = 0.f, pos = 0.f;
    #pragma unroll 4
    for (int t2 = 0; t2 < NT; t2++){
      float sc = a1v + g_a2[b*NT + t2] + bm;
      sc = fminf(fmaxf(sc, -10.f), 10.f);
      float tw = 1.0f / (fabsf((float)(t1 - t2)) + 1.0f);
      float w = expf(sc * tw);
      sum += w;
      if (t2 == t1) pos = w;
    }
    acc = logf(sum + 1e-8f) - logf(pos);
  }
  float lc = block_reduce(acc, red) * (1.0f/(NT*NB));
  float sv = (tid < NB*TM1) ? g_sync[tid] : 0.f;
  float ls = block_reduce(sv, red) * (1.0f/(NB*TM1));
  if (tid == 0) d_out[LOSS_OFF] = lc + ls;
}

// ---------------- launch ----------------
extern "C" void kernel_launch(void* const* d_in, const int* in_sizes, int n_in,
                              void* d_out, int out_size){
  const float* e_seq = (const float*)d_in[0];
  // d_in[1] = stockID (identity; folded out)
  const float* Ws_w  = (const float*)d_in[2];
  const float* Ws_b  = (const float*)d_in[3];
  const float* Wiota = (const float*)d_in[4];
  const float* w_eta = (const float*)d_in[5];
  const float* w_M   = (const float*)d_in[6];
  const float* b_M   = (const float*)d_in[7];
  const float* sc_W1 = (const float*)d_in[8];
  const float* sc_b1 = (const float*)d_in[9];
  const float* sc_W2 = (const float*)d_in[10];
  const float* sc_b2 = (const float*)d_in[11];
  const int*  perms  = (const int*)d_in[12];
  const int*  cidx   = (const int*)d_in[13];
  float* out = (float*)d_out;

  k_pre<<<41, 256>>>(Wiota, w_eta, perms);
  k_main<<<dim3(NI, NB), 256>>>(e_seq, Ws_w, Ws_b, w_eta, cidx, out);
  k_msum<<<dim3(NB*NT, NSPLIT), 128>>>(e_seq);
  k_mfinal<<<NB*NT, 256>>>(w_M, sc_W1, sc_b1, sc_W2, sc_b2, out);
  k_final<<<1, 256>>>(b_M, out);
}